// round 14
// baseline (speedup 1.0000x reference)
#include <cuda_runtime.h>
#include <cuda_bf16.h>
#include <cstdint>

#define B_ 32
#define T_ 2048
#define V_ 128
#define S_ 256
#define L_ 513            // 2*S+1
#define NEGV -1e30f
#define LOG2E 1.4426950408889634f
#define LN2   0.6931471805599453f
#define SENTBITS 0x3F800000u   // 1.0f; alphas are always <= ~0 or NEGV

// Scratch (no allocations allowed in kernel_launch)
__device__ float g_EL[B_ * T_ * 256];   // label emissions  lp2[t][lab[j]]  (64 MB)
__device__ float g_EB[B_ * T_];         // blank emissions  lp2[t][0]
__device__ float g_loss[B_];            // per-batch normalized loss

__device__ __forceinline__ float ex2(float x) {
    float y; asm("ex2.approx.ftz.f32 %0, %1;" : "=f"(y) : "f"(x)); return y;
}
__device__ __forceinline__ float lg2(float x) {
    float y; asm("lg2.approx.f32 %0, %1;" : "=f"(y) : "f"(x)); return y;
}

// ---------------------------------------------------------------------------
// Kernel 1: log2-softmax + emission gather. Warp per (b,t) row.
//   EL[row][j] = lp2[row][ gt[b][j] ],  EB[row] = lp2[row][0]
// ---------------------------------------------------------------------------
__global__ __launch_bounds__(128) void k_em(const float* __restrict__ pred,
                                            const int*   __restrict__ gt) {
    __shared__ float lprow[4][V_];
    int w    = threadIdx.x >> 5;
    int lane = threadIdx.x & 31;
    int row  = blockIdx.x * 4 + w;          // row = b*T + t
    int b    = row >> 11;

    const float4* p = reinterpret_cast<const float4*>(pred) + (size_t)row * (V_ / 4);
    float4 v = p[lane];
    float m = fmaxf(fmaxf(v.x, v.y), fmaxf(v.z, v.w));
#pragma unroll
    for (int o = 16; o; o >>= 1) m = fmaxf(m, __shfl_xor_sync(0xffffffffu, m, o));
    float wx = (v.x - m) * LOG2E, wy = (v.y - m) * LOG2E;
    float wz = (v.z - m) * LOG2E, ww = (v.w - m) * LOG2E;
    float s = ex2(wx) + ex2(wy) + ex2(wz) + ex2(ww);
#pragma unroll
    for (int o = 16; o; o >>= 1) s += __shfl_xor_sync(0xffffffffu, s, o);
    float l = lg2(s);

    lprow[w][lane * 4 + 0] = wx - l;
    lprow[w][lane * 4 + 1] = wy - l;
    lprow[w][lane * 4 + 2] = wz - l;
    lprow[w][lane * 4 + 3] = ww - l;
    __syncwarp();

    if (lane == 0) g_EB[row] = lprow[w][0];
    const int* lb = gt + b * S_;
#pragma unroll
    for (int k = 0; k < 8; k++) {
        int j = lane + k * 32;
        g_EL[(size_t)row * 256 + j] = lprow[w][lb[j]];
    }
}

// ---------------------------------------------------------------------------
// Kernel 2: systolic CTC DP. One CTA (256 thr) per batch element.
// Thread tid keeps even state s0=2*tid and odd s1=2*tid+1 IN REGISTERS.
// Per step the only cross-thread datum is the left neighbor's odd alpha:
//   - within a warp: __shfl_up 1
//   - across warps: write-once smem mailbox mbox[w][t] (sentinel-polled,
//     payload==flag, warps run skewed; NO __syncthreads in the loop)
// Emissions stream from g_EL/g_EB via an 8-deep register prefetch pipeline.
// ---------------------------------------------------------------------------
__global__ __launch_bounds__(256) void k_dp(const int* __restrict__ plen,
                                            const int* __restrict__ glen) {
    extern __shared__ float mbox[];          // [7][T_]  (57344 B)
    __shared__ float fin[L_];                // final alphas for readout

    int b    = blockIdx.x;
    int tid  = threadIdx.x;
    int wid  = tid >> 5;
    int lane = tid & 31;
    int il = plen[b];
    int tl = glen[b];

    const float* EL = g_EL + (size_t)b * T_ * 256;
    const float* EB = g_EB + (size_t)b * T_;

    unsigned mb_base = (unsigned)__cvta_generic_to_shared(mbox);

    // skip condition for odd state s1 = 2*tid+1 (label lab[tid])
    // (recompute from g_EL is impossible; use gt via plen? -> read labels once)
    // We derive skA by comparing emissions is unsafe; read gt directly:
    //   lab values live in g_EL construction; here we reload from the source.
    // (gt pointer passed via plen? No: we re-derive using EL equality is wrong.
    //  So gt is passed through glen? No — we simply reload labels below.)
    // NOTE: gt is reachable: it was bound in k_em; here we need lab[tid] and
    // lab[tid-1] only for equality. We pass gt as a kernel arg instead.
    // (see launch: k_dp(plen, glen) -> extended to include gt)
    // -- replaced below by the 3-arg version --
    (void)EL; (void)EB; (void)mb_base; (void)il; (void)tl; (void)fin;
    (void)wid; (void)lane;
}

// Real DP kernel (3-arg version with gt for the skip predicate)
__global__ __launch_bounds__(256) void k_dp3(const int* __restrict__ plen,
                                             const int* __restrict__ gt,
                                             const int* __restrict__ glen) {
    extern __shared__ float mbox[];          // [7][T_]  (57344 B)
    __shared__ float fin[L_];

    int b    = blockIdx.x;
    int tid  = threadIdx.x;
    int wid  = tid >> 5;
    int lane = tid & 31;
    int il = plen[b];
    int tl = glen[b];

    const float* EL = g_EL + (size_t)b * T_ * 256;
    const float* EB = g_EB + (size_t)b * T_;
    const int*   lab = gt + b * S_;

    unsigned mb_base = (unsigned)__cvta_generic_to_shared(mbox);

    bool skA  = (tid >= 1) && (lab[tid] != lab[tid - 1]);
    bool last = (tid == 255);

    // Init mailbox: all sentinel, except t=0 column = NEGV (alpha0 boundaries)
    for (int i = tid; i < 7 * T_; i += 256)
        mbox[i] = __uint_as_float(SENTBITS);
    __syncthreads();
    if (tid < 7) mbox[tid * T_ + 0] = NEGV;

    // alpha0 in registers
    float a0 = (tid == 0) ? EB[0] : NEGV;      // s=0: blank at t=0
    float a1 = (tid == 0) ? EL[0] : NEGV;      // s=1: lab[0] at t=0
    float a2 = NEGV;                           // s=512 (thread 255 only)

    __syncthreads();   // mailbox init visible before any producer writes

    // 8-deep emission prefetch pipeline
    float eL[8], eB[8];
#pragma unroll
    for (int d = 0; d < 8; d++) {
        int tt = 1 + d;
        bool ok = tt < il;
        eL[d] = ok ? __ldg(&EL[(size_t)tt * 256 + tid]) : 0.0f;
        eB[d] = ok ? __ldg(&EB[tt]) : 0.0f;
    }

    for (int tb = 1; tb < il; tb += 8) {
#pragma unroll
        for (int d = 0; d < 8; d++) {
            int t = tb + d;
            if (t >= il) break;

            // left neighbor's odd alpha (s0-1)
            float pl = __shfl_up_sync(0xffffffffu, a1, 1);
            if (lane == 0) {
                if (wid == 0) {
                    pl = NEGV;
                } else {
                    unsigned off = mb_base + (unsigned)(((wid - 1) * T_ + (t - 1)) * 4);
                    float v;
                    do {
                        asm volatile("ld.volatile.shared.f32 %0, [%1];" : "=f"(v) : "r"(off));
                    } while (__float_as_uint(v) == SENTBITS);
                    pl = v;
                }
            }

            // even s0: LSE2(a0, pl) + blank emission
            float m0 = fmaxf(a0, pl);
            float r0 = m0 + lg2(ex2(a0 - m0) + ex2(pl - m0)) + eB[d];

            // odd s1: LSE3(a1, a0, sk?pl) + label emission
            float a3 = skA ? pl : NEGV;
            float m1 = fmaxf(fmaxf(a1, a0), a3);
            float r1 = m1 + lg2(ex2(a1 - m1) + ex2(a0 - m1) + ex2(a3 - m1)) + eL[d];

            if (last) {   // s=512: LSE2(a2, a1) + blank
                float m2 = fmaxf(a2, a1);
                a2 = m2 + lg2(ex2(a2 - m2) + ex2(a1 - m2)) + eB[d];
            }

            // publish boundary for right warp (write-once slot)
            if (lane == 31 && wid < 7) {
                unsigned off = mb_base + (unsigned)((wid * T_ + t) * 4);
                asm volatile("st.volatile.shared.f32 [%0], %1;" :: "r"(off), "f"(r1));
            }

            a0 = r0;
            a1 = r1;

            // prefetch emissions for t+8
            int tn = t + 8;
            bool ok = tn < il;
            eL[d] = ok ? __ldg(&EL[(size_t)tn * 256 + tid]) : 0.0f;
            eB[d] = ok ? __ldg(&EB[tn]) : 0.0f;
        }
    }

    // gather final alphas and reduce
    fin[2 * tid]     = a0;
    fin[2 * tid + 1] = a1;
    if (last) fin[512] = a2;
    __syncthreads();

    if (tid == 0) {
        int ls = 2 * tl;
        float a = fin[ls];
        float c = fin[ls - 1];
        float m = fmaxf(a, c);
        float lae2 = m + lg2(ex2(a - m) + ex2(c - m));
        float lo2 = -lae2 * LN2;
        if (!(lo2 < 1e10f)) lo2 = 0.0f;          // zero_infinity
        g_loss[b] = lo2 / (float)tl;
    }
}

// ---------------------------------------------------------------------------
// Kernel 3: deterministic mean over batch
// ---------------------------------------------------------------------------
__global__ void k_reduce(float* out) {
    float v = (threadIdx.x < B_) ? g_loss[threadIdx.x] : 0.0f;
#pragma unroll
    for (int o = 16; o; o >>= 1) v += __shfl_xor_sync(0xffffffffu, v, o);
    if (threadIdx.x == 0) out[0] = v / (float)B_;
}

// ---------------------------------------------------------------------------
extern "C" void kernel_launch(void* const* d_in, const int* in_sizes, int n_in,
                              void* d_out, int out_size) {
    const float* pred = (const float*)d_in[0];
    const int*   plen = (const int*)d_in[1];
    const int*   gt   = (const int*)d_in[2];
    const int*   glen = (const int*)d_in[3];

    static bool attr_done = false;
    if (!attr_done) {
        cudaFuncSetAttribute(k_dp3, cudaFuncAttributeMaxDynamicSharedMemorySize,
                             7 * T_ * (int)sizeof(float));
        attr_done = true;
    }

    k_em<<<(B_ * T_) / 4, 128>>>(pred, gt);
    k_dp3<<<B_, 256, 7 * T_ * (int)sizeof(float)>>>(plen, gt, glen);
    k_reduce<<<1, 32>>>((float*)d_out);
}